// round 10
// baseline (speedup 1.0000x reference)
#include <cuda_runtime.h>
#include <cuda_bf16.h>
#include <math.h>
#include <stdint.h>

#define BATCH 8
#define TT    2048
#define DM    512
#define NS    64
#define BT    (BATCH * TT)   /* 16384 */
#define NN    (NS * NS)      /* 4096  */
#define CHL   32             /* scan chunk length */
#define CHC   (TT / CHL)     /* 64 chunks per batch */
#define NCH   (BATCH * CHC)  /* 512 total chunks */

// ---------------- scratch (static device arrays; no allocation) ----------------
__device__ __align__(16) __nv_bfloat16 g_Ahi[(size_t)BT * NN];  // 134 MB
__device__ __align__(16) __nv_bfloat16 g_Alo[(size_t)BT * NN];  // 134 MB
__device__ float g_d[BT * NS];
__device__ float g_Bu[BT * NS];
__device__ __align__(16) __nv_bfloat16 g_hshi[BT * NS];
__device__ __align__(16) __nv_bfloat16 g_hslo[BT * NS];
__device__ __align__(16) float g_M[(size_t)NCH * NN];           // 8.4 MB chunk propagators
__device__ __align__(16) float g_v[NCH * NS];
__device__ __align__(16) float g_Hs[NCH * NS];
__device__ __align__(16) __nv_bfloat16 g_uhi[(size_t)BT * DM];
__device__ __align__(16) __nv_bfloat16 g_ulo[(size_t)BT * DM];
__device__ __align__(16) __nv_bfloat16 g_whi[(size_t)NN * DM];
__device__ __align__(16) __nv_bfloat16 g_wlo[(size_t)NN * DM];
__device__ __align__(16) __nv_bfloat16 g_w2hi[128 * DM];        // [Wd;Wb]
__device__ __align__(16) __nv_bfloat16 g_w2lo[128 * DM];
__device__ __align__(16) __nv_bfloat16 g_chi[DM * NS];          // C_w
__device__ __align__(16) __nv_bfloat16 g_clo[DM * NS];

// ---------------- helpers ----------------
__device__ __forceinline__ uint32_t smem_u32(const void* p) {
    uint32_t a;
    asm("{ .reg .u64 t; cvta.to.shared.u64 t, %1; cvt.u32.u64 %0, t; }" : "=r"(a) : "l"(p));
    return a;
}

__device__ __forceinline__ void ldm_x4(uint32_t* r, uint32_t addr) {
    asm volatile("ldmatrix.sync.aligned.m8n8.x4.shared.b16 {%0,%1,%2,%3}, [%4];"
                 : "=r"(r[0]), "=r"(r[1]), "=r"(r[2]), "=r"(r[3]) : "r"(addr));
}

__device__ __forceinline__ void mma_bf16(float* c, const uint32_t* a, const uint32_t* b) {
    asm volatile(
        "mma.sync.aligned.m16n8k16.row.col.f32.bf16.bf16.f32 "
        "{%0,%1,%2,%3}, {%4,%5,%6,%7}, {%8,%9}, {%0,%1,%2,%3};"
        : "+f"(c[0]), "+f"(c[1]), "+f"(c[2]), "+f"(c[3])
        : "r"(a[0]), "r"(a[1]), "r"(a[2]), "r"(a[3]), "r"(b[0]), "r"(b[1]));
}

__device__ __forceinline__ void cp16(uint32_t dst, const void* src) {
    asm volatile("cp.async.cg.shared.global [%0], [%1], 16;" :: "r"(dst), "l"(src));
}
#define CP_COMMIT() asm volatile("cp.async.commit_group;" ::: "memory")
#define CP_WAIT1()  asm volatile("cp.async.wait_group 1;" ::: "memory")
#define CP_WAIT0()  asm volatile("cp.async.wait_group 0;" ::: "memory")

__device__ __forceinline__ float2 bf2f(uint32_t p) {
    float2 r;
    r.x = __uint_as_float(p << 16);
    r.y = __uint_as_float(p & 0xffff0000u);
    return r;
}

__device__ __forceinline__ float dot8(uint4 p, const float* hk) {
    float s = 0.f;
    float2 f;
    f = bf2f(p.x); s = fmaf(f.x, hk[0], s); s = fmaf(f.y, hk[1], s);
    f = bf2f(p.y); s = fmaf(f.x, hk[2], s); s = fmaf(f.y, hk[3], s);
    f = bf2f(p.z); s = fmaf(f.x, hk[4], s); s = fmaf(f.y, hk[5], s);
    f = bf2f(p.w); s = fmaf(f.x, hk[6], s); s = fmaf(f.y, hk[7], s);
    return s;
}

__device__ __forceinline__ uint32_t pack_hl(float v0, float v1, uint32_t& lo) {
    __nv_bfloat16 h0 = __float2bfloat16(v0), h1 = __float2bfloat16(v1);
    float r0 = v0 - __bfloat162float(h0), r1 = v1 - __bfloat162float(h1);
    __nv_bfloat16 l0 = __float2bfloat16(r0), l1 = __float2bfloat16(r1);
    lo = (uint32_t)__bfloat16_as_ushort(l0) | ((uint32_t)__bfloat16_as_ushort(l1) << 16);
    return (uint32_t)__bfloat16_as_ushort(h0) | ((uint32_t)__bfloat16_as_ushort(h1) << 16);
}

// =====================================================================
// K0: fp32 -> (bf16 hi, bf16 lo) split
// =====================================================================
__global__ void __launch_bounds__(256) k0_cvt(
    const float* __restrict__ src, __nv_bfloat16* __restrict__ hi,
    __nv_bfloat16* __restrict__ lo, int n4)
{
    int i = blockIdx.x * 256 + threadIdx.x;
    if (i >= n4) return;
    float4 v = ((const float4*)src)[i];
    float f[4] = {v.x, v.y, v.z, v.w};
    ushort4 H, L;
    unsigned short hs[4], ls[4];
#pragma unroll
    for (int j = 0; j < 4; j++) {
        __nv_bfloat16 h = __float2bfloat16(f[j]);
        float r = f[j] - __bfloat162float(h);
        hs[j] = __bfloat16_as_ushort(h);
        ls[j] = __bfloat16_as_ushort(__float2bfloat16(r));
    }
    H.x = hs[0]; H.y = hs[1]; H.z = hs[2]; H.w = hs[3];
    L.x = ls[0]; L.y = ls[1]; L.z = ls[2]; L.w = ls[3];
    ((ushort4*)hi)[i] = H;
    ((ushort4*)lo)[i] = L;
}

#define K2_STRIDE_B 144

// =====================================================================
// K1t (HMMA): d = sigmoid(u@Wd^T+bd), Bu = u@Wb^T+bb.
// =====================================================================
#define K1_TILE_B   (128 * K2_STRIDE_B)   /* 18432 */
#define K1_STAGE_B  (4 * K1_TILE_B)       /* 73728 */
#define K1_SMEM     (2 * K1_STAGE_B)      /* 147456 */

__global__ void __launch_bounds__(256, 1) k1t_dbu(
    const float* __restrict__ bd, const float* __restrict__ bb)
{
    extern __shared__ char sm[];
    const uint32_t sb = smem_u32(sm);

    const int tid  = threadIdx.x;
    const int warp = tid >> 5;
    const int lane = tid & 31;
    const int wm   = warp >> 2;
    const int wn   = warp & 3;
    const int mb   = blockIdx.x * 128;

    const __nv_bfloat16* srcs[4] = {
        g_uhi + (size_t)mb * DM, g_ulo + (size_t)mb * DM, g_w2hi, g_w2lo };

    float acc[4][4][4];
#pragma unroll
    for (int i = 0; i < 4; i++)
#pragma unroll
        for (int j = 0; j < 4; j++)
#pragma unroll
            for (int q = 0; q < 4; q++) acc[i][j][q] = 0.f;

    const int a_row = (lane & 15);
    const int a_chk = (lane >> 4);
    const int b_row = (lane & 7) + ((lane >> 4) << 3);
    const int b_chk = ((lane >> 3) & 1);

#pragma unroll
    for (int t = 0; t < 4; t++) {
        const __nv_bfloat16* s = srcs[t];
#pragma unroll
        for (int j = 0; j < 4; j++) {
            int f = tid + 256 * j;
            int row = f >> 3, c = f & 7;
            cp16(sb + t * K1_TILE_B + row * K2_STRIDE_B + c * 16,
                 s + (size_t)row * DM + c * 8);
        }
    }
    CP_COMMIT();

    for (int ch = 0; ch < 8; ch++) {
        const uint32_t sbase = sb + (ch & 1) * K1_STAGE_B;
        if (ch < 7) {
            const uint32_t nbase = sb + ((ch + 1) & 1) * K1_STAGE_B;
            const int k0g = (ch + 1) * 64;
#pragma unroll
            for (int t = 0; t < 4; t++) {
                const __nv_bfloat16* s = srcs[t];
#pragma unroll
                for (int j = 0; j < 4; j++) {
                    int f = tid + 256 * j;
                    int row = f >> 3, c = f & 7;
                    cp16(nbase + t * K1_TILE_B + row * K2_STRIDE_B + c * 16,
                         s + (size_t)row * DM + k0g + c * 8);
                }
            }
            CP_COMMIT();
            CP_WAIT1();
        } else {
            CP_WAIT0();
        }
        __syncthreads();

        const uint32_t sAhi = sbase;
        const uint32_t sAlo = sbase + K1_TILE_B;
        const uint32_t sBhi = sbase + 2 * K1_TILE_B;
        const uint32_t sBlo = sbase + 3 * K1_TILE_B;

#pragma unroll
        for (int k16 = 0; k16 < 4; k16++) {
            const int kc = k16 * 2;
            uint32_t bh[4][2], bl[4][2];
#pragma unroll
            for (int g = 0; g < 2; g++) {
                uint32_t r[4];
                ldm_x4(r, sBhi + (wn * 32 + g * 16 + b_row) * K2_STRIDE_B + (kc + b_chk) * 16);
                bh[2 * g][0] = r[0]; bh[2 * g][1] = r[1];
                bh[2 * g + 1][0] = r[2]; bh[2 * g + 1][1] = r[3];
                ldm_x4(r, sBlo + (wn * 32 + g * 16 + b_row) * K2_STRIDE_B + (kc + b_chk) * 16);
                bl[2 * g][0] = r[0]; bl[2 * g][1] = r[1];
                bl[2 * g + 1][0] = r[2]; bl[2 * g + 1][1] = r[3];
            }
#pragma unroll
            for (int mi = 0; mi < 4; mi++) {
                uint32_t ah[4], al[4];
                ldm_x4(ah, sAhi + (wm * 64 + mi * 16 + a_row) * K2_STRIDE_B + (kc + a_chk) * 16);
                ldm_x4(al, sAlo + (wm * 64 + mi * 16 + a_row) * K2_STRIDE_B + (kc + a_chk) * 16);
#pragma unroll
                for (int ni = 0; ni < 4; ni++) {
                    mma_bf16(acc[mi][ni], ah, bh[ni]);
                    mma_bf16(acc[mi][ni], ah, bl[ni]);
                    mma_bf16(acc[mi][ni], al, bh[ni]);
                }
            }
        }
        __syncthreads();
    }

    const int mr = mb + wm * 64 + (lane >> 2);
    const int nc0 = wn * 32 + (lane & 3) * 2;
#pragma unroll
    for (int mi = 0; mi < 4; mi++) {
#pragma unroll
        for (int ni = 0; ni < 4; ni++) {
            int n = nc0 + ni * 8;
#pragma unroll
            for (int half = 0; half < 2; half++) {
                int m = mr + mi * 16 + half * 8;
                float v0 = acc[mi][ni][2 * half];
                float v1 = acc[mi][ni][2 * half + 1];
                if (n < 64) {
                    v0 = 1.f / (1.f + expf(-(v0 + __ldg(bd + n))));
                    v1 = 1.f / (1.f + expf(-(v1 + __ldg(bd + n + 1))));
                    *(float2*)(g_d + (size_t)m * NS + n) = make_float2(v0, v1);
                } else {
                    v0 += __ldg(bb + n - 64);
                    v1 += __ldg(bb + n - 63);
                    *(float2*)(g_Bu + (size_t)m * NS + (n - 64)) = make_float2(v0, v1);
                }
            }
        }
    }
}

// =====================================================================
// K2 (HMMA, cp.async 2-stage, 128x128 tile, 147KB smem so k3a can
// co-reside): A = tanh(u@W_A^T + b)/8, diag<-d, output bf16 hi/lo.
// y0 = quarter offset (grid.y covers a quarter of BT/128).
// =====================================================================
#define K2_TILE_B   (128 * K2_STRIDE_B)   /* 18432 */
#define K2_STAGE_B  (4 * K2_TILE_B)       /* 73728 */
#define K2_SMEM     (2 * K2_STAGE_B)      /* 147456 */

__global__ void __launch_bounds__(256, 1) k2h_A(const float* __restrict__ ba, int y0)
{
    extern __shared__ char sm[];
    const uint32_t sb = smem_u32(sm);

    const int tid  = threadIdx.x;
    const int warp = tid >> 5;
    const int lane = tid & 31;
    const int wm   = warp >> 2;
    const int wn   = warp & 3;
    const int nb   = blockIdx.x * 128;
    const int mb   = (blockIdx.y + y0) * 128;

    const __nv_bfloat16* srcs[4] = {
        g_uhi + (size_t)mb * DM, g_ulo + (size_t)mb * DM,
        g_whi + (size_t)nb * DM, g_wlo + (size_t)nb * DM };

    float acc[4][4][4];
#pragma unroll
    for (int i = 0; i < 4; i++)
#pragma unroll
        for (int j = 0; j < 4; j++)
#pragma unroll
            for (int q = 0; q < 4; q++) acc[i][j][q] = 0.f;

    const int a_row = (lane & 15);
    const int a_chk = (lane >> 4);
    const int b_row = (lane & 7) + ((lane >> 4) << 3);
    const int b_chk = ((lane >> 3) & 1);

#pragma unroll
    for (int t = 0; t < 4; t++) {
        const __nv_bfloat16* s = srcs[t];
#pragma unroll
        for (int j = 0; j < 4; j++) {
            int f = tid + 256 * j;
            int row = f >> 3, c = f & 7;
            cp16(sb + t * K2_TILE_B + row * K2_STRIDE_B + c * 16,
                 s + (size_t)row * DM + c * 8);
        }
    }
    CP_COMMIT();

    for (int ch = 0; ch < 8; ch++) {
        const uint32_t sbase = sb + (ch & 1) * K2_STAGE_B;
        if (ch < 7) {
            const uint32_t nbase = sb + ((ch + 1) & 1) * K2_STAGE_B;
            const int k0g = (ch + 1) * 64;
#pragma unroll
            for (int t = 0; t < 4; t++) {
                const __nv_bfloat16* s = srcs[t];
#pragma unroll
                for (int j = 0; j < 4; j++) {
                    int f = tid + 256 * j;
                    int row = f >> 3, c = f & 7;
                    cp16(nbase + t * K2_TILE_B + row * K2_STRIDE_B + c * 16,
                         s + (size_t)row * DM + k0g + c * 8);
                }
            }
            CP_COMMIT();
            CP_WAIT1();
        } else {
            CP_WAIT0();
        }
        __syncthreads();

        const uint32_t sAhi = sbase;
        const uint32_t sAlo = sbase + K2_TILE_B;
        const uint32_t sBhi = sbase + 2 * K2_TILE_B;
        const uint32_t sBlo = sbase + 3 * K2_TILE_B;

#pragma unroll
        for (int k16 = 0; k16 < 4; k16++) {
            const int kc = k16 * 2;
            uint32_t bh[4][2], bl[4][2];
#pragma unroll
            for (int g = 0; g < 2; g++) {
                uint32_t r[4];
                ldm_x4(r, sBhi + (wn * 32 + g * 16 + b_row) * K2_STRIDE_B + (kc + b_chk) * 16);
                bh[2 * g][0] = r[0]; bh[2 * g][1] = r[1];
                bh[2 * g + 1][0] = r[2]; bh[2 * g + 1][1] = r[3];
                ldm_x4(r, sBlo + (wn * 32 + g * 16 + b_row) * K2_STRIDE_B + (kc + b_chk) * 16);
                bl[2 * g][0] = r[0]; bl[2 * g][1] = r[1];
                bl[2 * g + 1][0] = r[2]; bl[2 * g + 1][1] = r[3];
            }
#pragma unroll
            for (int mi = 0; mi < 4; mi++) {
                uint32_t ah[4], al[4];
                ldm_x4(ah, sAhi + (wm * 64 + mi * 16 + a_row) * K2_STRIDE_B + (kc + a_chk) * 16);
                ldm_x4(al, sAlo + (wm * 64 + mi * 16 + a_row) * K2_STRIDE_B + (kc + a_chk) * 16);
#pragma unroll
                for (int ni = 0; ni < 4; ni++) {
                    mma_bf16(acc[mi][ni], ah, bh[ni]);
                    mma_bf16(acc[mi][ni], ah, bl[ni]);
                    mma_bf16(acc[mi][ni], al, bh[ni]);
                }
            }
        }
        __syncthreads();
    }

    // epilogue: bias + tanh*0.125, diag <- d, write bf16 hi/lo pairs
    const int mr = mb + wm * 64 + (lane >> 2);
    const int nc0 = nb + wn * 32 + (lane & 3) * 2;
#pragma unroll
    for (int mi = 0; mi < 4; mi++) {
#pragma unroll
        for (int ni = 0; ni < 4; ni++) {
            int n = nc0 + ni * 8;
            float bias0 = __ldg(ba + n), bias1 = __ldg(ba + n + 1);
            int i0 = n / 64, j0 = n % 64;
            int i1 = (n + 1) / 64, j1 = (n + 1) % 64;
#pragma unroll
            for (int half = 0; half < 2; half++) {
                int m = mr + mi * 16 + half * 8;
                float v0 = tanhf(acc[mi][ni][2 * half] + bias0) * 0.125f;
                float v1 = tanhf(acc[mi][ni][2 * half + 1] + bias1) * 0.125f;
                if (i0 == j0) v0 = g_d[(size_t)m * NS + i0];
                if (i1 == j1) v1 = g_d[(size_t)m * NS + i1];
                uint32_t lo, hi = pack_hl(v0, v1, lo);
                *(uint32_t*)(g_Ahi + (size_t)m * NN + n) = hi;
                *(uint32_t*)(g_Alo + (size_t)m * NN + n) = lo;
            }
        }
    }
}

// =====================================================================
// K3a (pass 1): per-chunk propagator M_c (tensor, bf16 3-prod) + v_c.
// b0 = batch offset (grid.y covers 2 batches per quarter launch).
// =====================================================================
#define P1_SA(s)   ((s) * 18432)
#define P1_SALO(s) ((s) * 18432 + 9216)
#define P1_MTH     36864
#define P1_MTL     46080
#define P1_SV      55296
#define P1_SBU     55808
#define P1_SMEM    56320

__global__ void __launch_bounds__(256) k3a_prop(int b0)
{
    extern __shared__ char sm[];
    const uint32_t sb = smem_u32(sm);
    const int tid = threadIdx.x, warp = tid >> 5, lane = tid & 31;
    const int wm = warp >> 1, wn = warp & 1;
    const int chunk = blockIdx.x, b = blockIdx.y + b0;
    const int cid = b * CHC + chunk;
    const size_t tbase = (size_t)b * TT + (size_t)chunk * CHL;
    const __nv_bfloat16* Ahi = g_Ahi + tbase * NN;
    const __nv_bfloat16* Alo = g_Alo + tbase * NN;
    const float* Bu = g_Bu + tbase * NS;

    for (int f = tid; f < 4096; f += 256) {
        int j = f >> 6, ii = f & 63;
        *(unsigned short*)(sm + P1_MTH + j * 144 + ii * 2) =
            (j == ii) ? (unsigned short)0x3F80 : (unsigned short)0;
        *(unsigned short*)(sm + P1_MTL + j * 144 + ii * 2) = 0;
    }
    if (tid < 64) ((float*)(sm + P1_SV))[tid] = 0.f;

#pragma unroll
    for (int j = 0; j < 2; j++) {
        int f = tid + 256 * j;
        int r2 = f >> 3, c2 = f & 7;
        cp16(sb + P1_SA(0) + r2 * 144 + c2 * 16, Ahi + (size_t)r2 * 64 + c2 * 8);
        cp16(sb + P1_SALO(0) + r2 * 144 + c2 * 16, Alo + (size_t)r2 * 64 + c2 * 8);
    }
    if (tid < 16) cp16(sb + P1_SBU + tid * 16, Bu + tid * 4);
    CP_COMMIT();
    __syncthreads();

    const int a_row = lane & 15, a_chk = lane >> 4;
    const int b_row = (lane & 7) + ((lane >> 4) << 3);
    const int b_chk = (lane >> 3) & 1;
    const int vi = tid >> 2, vq = tid & 3;

    float acc[4][4];

    for (int t = 0; t < CHL; t++) {
        const int s = t & 1;
        if (t < CHL - 1) {
            const int s1 = s ^ 1;
#pragma unroll
            for (int j = 0; j < 2; j++) {
                int f = tid + 256 * j;
                int r2 = f >> 3, c2 = f & 7;
                cp16(sb + P1_SA(s1) + r2 * 144 + c2 * 16,
                     Ahi + (size_t)(t + 1) * NN + r2 * 64 + c2 * 8);
                cp16(sb + P1_SALO(s1) + r2 * 144 + c2 * 16,
                     Alo + (size_t)(t + 1) * NN + r2 * 64 + c2 * 8);
            }
            if (tid < 16) cp16(sb + P1_SBU + s1 * 256 + tid * 16,
                               Bu + (size_t)(t + 1) * NS + tid * 4);
            CP_COMMIT();
            CP_WAIT1();
        } else {
            CP_WAIT0();
        }
        __syncthreads();

#pragma unroll
        for (int ni = 0; ni < 4; ni++)
#pragma unroll
            for (int q = 0; q < 4; q++) acc[ni][q] = 0.f;

        const uint32_t sAh = sb + P1_SA(s), sAl = sb + P1_SALO(s);
#pragma unroll
        for (int k16 = 0; k16 < 4; k16++) {
            const int kc = k16 * 2;
            uint32_t bh[4][2], bl[4][2];
#pragma unroll
            for (int g = 0; g < 2; g++) {
                uint32_t r[4];
                ldm_x4(r, sb + P1_MTH + (wn * 32 + g * 16 + b_row) * 144 + (kc + b_chk) * 16);
                bh[2 * g][0] = r[0]; bh[2 * g][1] = r[1];
                bh[2 * g + 1][0] = r[2]; bh[2 * g + 1][1] = r[3];
                ldm_x4(r, sb + P1_MTL + (wn * 32 + g * 16 + b_row) * 144 + (kc + b_chk) * 16);
                bl[2 * g][0] = r[0]; bl[2 * g][1] = r[1];
                bl[2 * g + 1][0] = r[2]; bl[2 * g + 1][1] = r[3];
            }
            uint32_t ah[4], al[4];
            ldm_x4(ah, sAh + (wm * 16 + a_row) * 144 + (kc + a_chk) * 16);
            ldm_x4(al, sAl + (wm * 16 + a_row) * 144 + (kc + a_chk) * 16);
#pragma unroll
            for (int ni = 0; ni < 4; ni++) mma_bf16(acc[ni], ah, bh[ni]);
#pragma unroll
            for (int ni = 0; ni < 4; ni++) mma_bf16(acc[ni], ah, bl[ni]);
#pragma unroll
            for (int ni = 0; ni < 4; ni++) mma_bf16(acc[ni], al, bh[ni]);
        }

        const char* pA = sm + P1_SA(s) + vi * 144 + vq * 32;
        uint4 vh0 = ((const uint4*)pA)[0], vh1 = ((const uint4*)pA)[1];
        const char* pL = sm + P1_SALO(s) + vi * 144 + vq * 32;
        uint4 vl0 = ((const uint4*)pL)[0], vl1 = ((const uint4*)pL)[1];
        const float* svp = (const float*)(sm + P1_SV) + s * 64 + vq * 16;
        float hk[16];
#pragma unroll
        for (int j = 0; j < 4; j++) {
            float4 hv = ((const float4*)svp)[j];
            hk[4 * j] = hv.x; hk[4 * j + 1] = hv.y; hk[4 * j + 2] = hv.z; hk[4 * j + 3] = hv.w;
        }
        float part = dot8(vh0, hk) + dot8(vh1, hk + 8) + dot8(vl0, hk) + dot8(vl1, hk + 8);
        part += __shfl_xor_sync(0xffffffffu, part, 1);
        part += __shfl_xor_sync(0xffffffffu, part, 2);
        float bu = 0.f;
        if (vq == 0) bu = ((const float*)(sm + P1_SBU))[s * 64 + vi];
        __syncthreads();

#pragma unroll
        for (int ni = 0; ni < 4; ni++) {
            int j0 = wn * 32 + ni * 8 + (lane & 3) * 2;
            int i0 = wm * 16 + (lane >> 2);
#pragma unroll
            for (int e = 0; e < 4; e++) {
                int jj = j0 + (e & 1);
                int ii = i0 + (e >> 1) * 8;
                float v = acc[ni][e];
                __nv_bfloat16 hbf = __float2bfloat16(v);
                float r = v - __bfloat162float(hbf);
                *(unsigned short*)(sm + P1_MTH + jj * 144 + ii * 2) = __bfloat16_as_ushort(hbf);
                *(unsigned short*)(sm + P1_MTL + jj * 144 + ii * 2) =
                    __bfloat16_as_ushort(__float2bfloat16(r));
            }
        }
        if (vq == 0) ((float*)(sm + P1_SV))[(s ^ 1) * 64 + vi] = part + bu;
        __syncthreads();
    }

#pragma unroll
    for (int ni = 0; ni < 4; ni++) {
        int j0 = wn * 32 + ni * 8 + (lane & 3) * 2;
        int i0 = wm * 16 + (lane >> 2);
        *(float2*)(g_M + (size_t)cid * NN + (size_t)i0 * 64 + j0) = make_float2(acc[ni][0], acc[ni][1]);
        *(float2*)(g_M + (size_t)cid * NN + (size_t)(i0 + 8) * 64 + j0) = make_float2(acc[ni][2], acc[ni][3]);
    }
    if (tid < 64) g_v[(size_t)cid * NS + tid] = ((const float*)(sm + P1_SV))[tid];
}

// =====================================================================
// K3b (pass 2): serial combine across chunks per batch.
// =====================================================================
__global__ void __launch_bounds__(256) k3b_comb()
{
    const int b = blockIdx.x, tid = threadIdx.x;
    const int i = tid >> 2, q = tid & 3;
    __shared__ float H[64];
    if (tid < 64) H[tid] = 0.f;
    __syncthreads();

    const float* Mb = g_M + (size_t)b * CHC * NN + (size_t)i * 64 + q * 16;
    const float* vb = g_v + (size_t)b * CHC * NS + i;

    float4 c0, c1, c2, c3, d0, d1, d2, d3;
    float4 e0 = make_float4(0, 0, 0, 0), e1 = e0, e2 = e0, e3 = e0;
    float vc = 0.f, vn = 0.f, ve = 0.f;

    {
        const float4* p = (const float4*)Mb;
        c0 = p[0]; c1 = p[1]; c2 = p[2]; c3 = p[3];
        p = (const float4*)(Mb + NN);
        d0 = p[0]; d1 = p[1]; d2 = p[2]; d3 = p[3];
        if (q == 0) { vc = vb[0]; vn = vb[NS]; }
    }

    for (int c = 0; c < CHC; c++) {
        if (c + 2 < CHC) {
            const float4* p = (const float4*)(Mb + (size_t)(c + 2) * NN);
            e0 = p[0]; e1 = p[1]; e2 = p[2]; e3 = p[3];
            if (q == 0) ve = vb[(size_t)(c + 2) * NS];
        }
        float hst = 0.f;
        if (tid < 64) hst = H[tid];
        const float* hv = H + q * 16;
        float4 h0 = *(const float4*)(hv);
        float4 h1 = *(const float4*)(hv + 4);
        float4 h2 = *(const float4*)(hv + 8);
        float4 h3 = *(const float4*)(hv + 12);

        float p4 = c0.x * h0.x + c0.y * h0.y + c0.z * h0.z + c0.w * h0.w;
        p4 += c1.x * h1.x + c1.y * h1.y + c1.z * h1.z + c1.w * h1.w;
        p4 += c2.x * h2.x + c2.y * h2.y + c2.z * h2.z + c2.w * h2.w;
        p4 += c3.x * h3.x + c3.y * h3.y + c3.z * h3.z + c3.w * h3.w;
        p4 += __shfl_xor_sync(0xffffffffu, p4, 1);
        p4 += __shfl_xor_sync(0xffffffffu, p4, 2);
        __syncthreads();

        if (tid < 64) g_Hs[(size_t)(b * CHC + c) * NS + tid] = hst;
        if (q == 0) H[i] = p4 + vc;
        __syncthreads();

        c0 = d0; c1 = d1; c2 = d2; c3 = d3;
        d0 = e0; d1 = e1; d2 = e2; d3 = e3;
        vc = vn; vn = ve;
    }
}

// =====================================================================
// K3c (pass 3): local scans from true start states; emit hs hi/lo.
// =====================================================================
__global__ void __launch_bounds__(256) k3c_scan()
{
    const int chunk = blockIdx.x, b = blockIdx.y, tid = threadIdx.x;
    const int i = tid >> 2, q = tid & 3;
    const int cid = b * CHC + chunk;
    const size_t tbase = (size_t)b * TT + (size_t)chunk * CHL;

    __shared__ float h[2][64];
    if (tid < 64) h[0][tid] = g_Hs[(size_t)cid * NS + tid];
    __syncthreads();

    const __nv_bfloat16* Ah = g_Ahi + tbase * NN + (size_t)i * 64 + q * 16;
    const __nv_bfloat16* Al = g_Alo + tbase * NN + (size_t)i * 64 + q * 16;
    const float* BuB = g_Bu + tbase * NS + i;
    __nv_bfloat16* hsHi = g_hshi + tbase * NS + i;
    __nv_bfloat16* hsLo = g_hslo + tbase * NS + i;

    uint4 ch0, ch1, cl0, cl1, nh0, nh1, nl0, nl1;
    uint4 eh0 = make_uint4(0, 0, 0, 0), eh1 = eh0, el0 = eh0, el1 = eh0;
    float buc = 0.f, bun = 0.f, bue = 0.f;

    {
        ch0 = ((const uint4*)Ah)[0]; ch1 = ((const uint4*)Ah)[1];
        cl0 = ((const uint4*)Al)[0]; cl1 = ((const uint4*)Al)[1];
        nh0 = ((const uint4*)(Ah + NN))[0]; nh1 = ((const uint4*)(Ah + NN))[1];
        nl0 = ((const uint4*)(Al + NN))[0]; nl1 = ((const uint4*)(Al + NN))[1];
        if (q == 0) { buc = BuB[0]; bun = BuB[NS]; }
    }

    for (int t = 0; t < CHL; t++) {
        if (t + 2 < CHL) {
            eh0 = ((const uint4*)(Ah + (size_t)(t + 2) * NN))[0];
            eh1 = ((const uint4*)(Ah + (size_t)(t + 2) * NN))[1];
            el0 = ((const uint4*)(Al + (size_t)(t + 2) * NN))[0];
            el1 = ((const uint4*)(Al + (size_t)(t + 2) * NN))[1];
            if (q == 0) bue = BuB[(size_t)(t + 2) * NS];
        }
        const float* hv = h[t & 1] + q * 16;
        float hk[16];
#pragma unroll
        for (int j = 0; j < 4; j++) {
            float4 x = ((const float4*)hv)[j];
            hk[4 * j] = x.x; hk[4 * j + 1] = x.y; hk[4 * j + 2] = x.z; hk[4 * j + 3] = x.w;
        }
        float p4 = dot8(ch0, hk) + dot8(ch1, hk + 8) + dot8(cl0, hk) + dot8(cl1, hk + 8);
        p4 += __shfl_xor_sync(0xffffffffu, p4, 1);
        p4 += __shfl_xor_sync(0xffffffffu, p4, 2);

        if (q == 0) {
            float nh = p4 + buc;
            h[(t & 1) ^ 1][i] = nh;
            __nv_bfloat16 hb = __float2bfloat16(nh);
            hsHi[(size_t)t * NS] = hb;
            hsLo[(size_t)t * NS] = __float2bfloat16(nh - __bfloat162float(hb));
        }
        __syncthreads();

        ch0 = nh0; ch1 = nh1; cl0 = nl0; cl1 = nl1;
        nh0 = eh0; nh1 = eh1; nl0 = el0; nl1 = el1;
        buc = bun; bun = bue;
    }
}

// =====================================================================
// K4t (HMMA): out = hs @ C^T + D * u.
// =====================================================================
#define K4_TILE_B  (128 * K2_STRIDE_B)    /* 18432 */
#define K4_SMEM    (4 * K4_TILE_B)        /* 73728 */

__global__ void __launch_bounds__(256, 1) k4t_out(
    const float* __restrict__ Dv, const float* __restrict__ u,
    float* __restrict__ out)
{
    extern __shared__ char sm[];
    const uint32_t sb = smem_u32(sm);

    const int tid  = threadIdx.x;
    const int warp = tid >> 5;
    const int lane = tid & 31;
    const int wm   = warp >> 2;
    const int wn   = warp & 3;
    const int nb   = blockIdx.x * 128;
    const int mb   = blockIdx.y * 128;

    const __nv_bfloat16* srcs[4] = {
        g_hshi + (size_t)mb * NS, g_hslo + (size_t)mb * NS,
        g_chi + (size_t)nb * NS, g_clo + (size_t)nb * NS };

#pragma unroll
    for (int t = 0; t < 4; t++) {
        const __nv_bfloat16* s = srcs[t];
#pragma unroll
        for (int j = 0; j < 4; j++) {
            int f = tid + 256 * j;
            int row = f >> 3, c = f & 7;
            cp16(sb + t * K4_TILE_B + row * K2_STRIDE_B + c * 16,
                 s + (size_t)row * NS + c * 8);
        }
    }
    CP_COMMIT();
    CP_WAIT0();
    __syncthreads();

    float acc[4][4][4];
#pragma unroll
    for (int i = 0; i < 4; i++)
#pragma unroll
        for (int j = 0; j < 4; j++)
#pragma unroll
            for (int q = 0; q < 4; q++) acc[i][j][q] = 0.f;

    const int a_row = (lane & 15);
    const int a_chk = (lane >> 4);
    const int b_row = (lane & 7) + ((lane >> 4) << 3);
    const int b_chk = ((lane >> 3) & 1);

    const uint32_t sAhi = sb;
    const uint32_t sAlo = sb + K4_TILE_B;
    const uint32_t sBhi = sb + 2 * K4_TILE_B;
    const uint32_t sBlo = sb + 3 * K4_TILE_B;

#pragma unroll
    for (int k16 = 0; k16 < 4; k16++) {
        const int kc = k16 * 2;
        uint32_t bh[4][2], bl[4][2];
#pragma unroll
        for (int g = 0; g < 2; g++) {
            uint32_t r[4];
            ldm_x4(r, sBhi + (wn * 32 + g * 16 + b_row) * K2_STRIDE_B + (kc + b_chk) * 16);
            bh[2 * g][0] = r[0]; bh[2 * g][1] = r[1];
            bh[2 * g + 1][0] = r[2]; bh[2 * g + 1][1] = r[3];
            ldm_x4(r, sBlo + (wn * 32 + g * 16 + b_row) * K2_STRIDE_B + (kc + b_chk) * 16);
            bl[2 * g][0] = r[0]; bl[2 * g][1] = r[1];
            bl[2 * g + 1][0] = r[2]; bl[2 * g + 1][1] = r[3];
        }
#pragma unroll
        for (int mi = 0; mi < 4; mi++) {
            uint32_t ah[4], al[4];
            ldm_x4(ah, sAhi + (wm * 64 + mi * 16 + a_row) * K2_STRIDE_B + (kc + a_chk) * 16);
            ldm_x4(al, sAlo + (wm * 64 + mi * 16 + a_row) * K2_STRIDE_B + (kc + a_chk) * 16);
#pragma unroll
            for (int ni = 0; ni < 4; ni++) {
                mma_bf16(acc[mi][ni], ah, bh[ni]);
                mma_bf16(acc[mi][ni], ah, bl[ni]);
                mma_bf16(acc[mi][ni], al, bh[ni]);
            }
        }
    }

    const int mr = mb + wm * 64 + (lane >> 2);
    const int nc0 = nb + wn * 32 + (lane & 3) * 2;
#pragma unroll
    for (int mi = 0; mi < 4; mi++) {
#pragma unroll
        for (int ni = 0; ni < 4; ni++) {
            int n = nc0 + ni * 8;
            float d0 = __ldg(Dv + n), d1 = __ldg(Dv + n + 1);
#pragma unroll
            for (int half = 0; half < 2; half++) {
                int m = mr + mi * 16 + half * 8;
                float2 uu = *(const float2*)(u + (size_t)m * DM + n);
                float v0 = acc[mi][ni][2 * half] + d0 * uu.x;
                float v1 = acc[mi][ni][2 * half + 1] + d1 * uu.y;
                *(float2*)(out + (size_t)m * DM + n) = make_float2(v0, v1);
            }
        }
    }
}

// =====================================================================
extern "C" void kernel_launch(void* const* d_in, const int* in_sizes, int n_in,
                              void* d_out, int out_size)
{
    const float* u    = (const float*)d_in[0];
    const float* Wd_w = (const float*)d_in[1];
    const float* Wd_b = (const float*)d_in[2];
    const float* WA_w = (const float*)d_in[3];
    const float* WA_b = (const float*)d_in[4];
    const float* WB_w = (const float*)d_in[5];
    const float* WB_b = (const float*)d_in[6];
    const float* C_w  = (const float*)d_in[7];
    const float* Dv   = (const float*)d_in[8];
    float* out = (float*)d_out;

    static int init_done = 0;
    static cudaStream_t s1;
    static cudaEvent_t evQ[4], evJoin;
    if (!init_done) {
        cudaFuncSetAttribute(k2h_A, cudaFuncAttributeMaxDynamicSharedMemorySize, K2_SMEM);
        cudaFuncSetAttribute(k1t_dbu, cudaFuncAttributeMaxDynamicSharedMemorySize, K1_SMEM);
        cudaFuncSetAttribute(k4t_out, cudaFuncAttributeMaxDynamicSharedMemorySize, K4_SMEM);
        cudaFuncSetAttribute(k3a_prop, cudaFuncAttributeMaxDynamicSharedMemorySize, P1_SMEM);
        cudaStreamCreateWithFlags(&s1, cudaStreamNonBlocking);
        for (int i = 0; i < 4; i++) cudaEventCreateWithFlags(&evQ[i], cudaEventDisableTiming);
        cudaEventCreateWithFlags(&evJoin, cudaEventDisableTiming);
        init_done = 1;
    }

    __nv_bfloat16 *uhi, *ulo, *whi, *wlo, *w2hi, *w2lo, *chi, *clo;
    cudaGetSymbolAddress((void**)&uhi, g_uhi);
    cudaGetSymbolAddress((void**)&ulo, g_ulo);
    cudaGetSymbolAddress((void**)&whi, g_whi);
    cudaGetSymbolAddress((void**)&wlo, g_wlo);
    cudaGetSymbolAddress((void**)&w2hi, g_w2hi);
    cudaGetSymbolAddress((void**)&w2lo, g_w2lo);
    cudaGetSymbolAddress((void**)&chi, g_chi);
    cudaGetSymbolAddress((void**)&clo, g_clo);

    int n4u = (BT * DM) / 4;
    int n4w = (NN * DM) / 4;
    int n4s = (64 * DM) / 4;
    int n4c = (DM * NS) / 4;
    k0_cvt<<<(n4u + 255) / 256, 256>>>(u, uhi, ulo, n4u);
    k0_cvt<<<(n4w + 255) / 256, 256>>>(WA_w, whi, wlo, n4w);
    k0_cvt<<<(n4s + 255) / 256, 256>>>(Wd_w, w2hi, w2lo, n4s);
    k0_cvt<<<(n4s + 255) / 256, 256>>>(WB_w, w2hi + 64 * DM, w2lo + 64 * DM, n4s);
    k0_cvt<<<(n4c + 255) / 256, 256>>>(C_w, chi, clo, n4c);
    k1t_dbu<<<BT / 128, 256, K1_SMEM>>>(Wd_b, WB_b);

    // K2 in 4 quarters (each = 2 batches), events after each
    for (int q = 0; q < 4; q++) {
        k2h_A<<<dim3(NN / 128, 32), 256, K2_SMEM>>>(WA_b, q * 32);
        cudaEventRecord(evQ[q], 0);
    }

    // stream s1: k3a quarter after each K2 quarter, then k3b/k3c/k4
    for (int q = 0; q < 4; q++) {
        cudaStreamWaitEvent(s1, evQ[q], 0);
        k3a_prop<<<dim3(CHC, 2), 256, P1_SMEM, s1>>>(q * 2);
    }
    k3b_comb<<<BATCH, 256, 0, s1>>>();
    k3c_scan<<<dim3(CHC, BATCH), 256, 0, s1>>>();
    k4t_out<<<dim3(DM / 128, BT / 128), 256, K4_SMEM, s1>>>(Dv, u, out);
    cudaEventRecord(evJoin, s1);
    cudaStreamWaitEvent(0, evJoin, 0);
}

// round 12
// speedup vs baseline: 1.1237x; 1.1237x over previous
#include <cuda_runtime.h>
#include <cuda_bf16.h>
#include <math.h>
#include <stdint.h>

#define BATCH 8
#define TT    2048
#define DM    512
#define NS    64
#define BT    (BATCH * TT)   /* 16384 */
#define NN    (NS * NS)      /* 4096  */
#define CHL   32             /* scan chunk length */
#define CHC   (TT / CHL)     /* 64 chunks per batch */
#define NCH   (BATCH * CHC)  /* 512 total chunks */

// ---------------- scratch (static device arrays; no allocation) ----------------
__device__ __align__(16) __nv_bfloat16 g_Ahi[(size_t)BT * NN];  // 134 MB
__device__ __align__(16) __nv_bfloat16 g_Alo[(size_t)BT * NN];  // 134 MB
__device__ float g_d[BT * NS];
__device__ float g_Bu[BT * NS];
__device__ __align__(16) __nv_bfloat16 g_hshi[BT * NS];
__device__ __align__(16) __nv_bfloat16 g_hslo[BT * NS];
__device__ __align__(16) float g_M[(size_t)NCH * NN];           // 8.4 MB chunk propagators
__device__ __align__(16) float g_v[NCH * NS];
__device__ __align__(16) float g_Hs[NCH * NS];
__device__ __align__(16) __nv_bfloat16 g_uhi[(size_t)BT * DM];
__device__ __align__(16) __nv_bfloat16 g_ulo[(size_t)BT * DM];
__device__ __align__(16) __nv_bfloat16 g_whi[(size_t)NN * DM];
__device__ __align__(16) __nv_bfloat16 g_wlo[(size_t)NN * DM];
__device__ __align__(16) __nv_bfloat16 g_w2hi[128 * DM];        // [Wd;Wb]
__device__ __align__(16) __nv_bfloat16 g_w2lo[128 * DM];
__device__ __align__(16) __nv_bfloat16 g_chi[DM * NS];          // C_w
__device__ __align__(16) __nv_bfloat16 g_clo[DM * NS];

// ---------------- helpers ----------------
__device__ __forceinline__ uint32_t smem_u32(const void* p) {
    uint32_t a;
    asm("{ .reg .u64 t; cvta.to.shared.u64 t, %1; cvt.u32.u64 %0, t; }" : "=r"(a) : "l"(p));
    return a;
}

__device__ __forceinline__ void ldm_x4(uint32_t* r, uint32_t addr) {
    asm volatile("ldmatrix.sync.aligned.m8n8.x4.shared.b16 {%0,%1,%2,%3}, [%4];"
                 : "=r"(r[0]), "=r"(r[1]), "=r"(r[2]), "=r"(r[3]) : "r"(addr));
}

__device__ __forceinline__ void mma_bf16(float* c, const uint32_t* a, const uint32_t* b) {
    asm volatile(
        "mma.sync.aligned.m16n8k16.row.col.f32.bf16.bf16.f32 "
        "{%0,%1,%2,%3}, {%4,%5,%6,%7}, {%8,%9}, {%0,%1,%2,%3};"
        : "+f"(c[0]), "+f"(c[1]), "+f"(c[2]), "+f"(c[3])
        : "r"(a[0]), "r"(a[1]), "r"(a[2]), "r"(a[3]), "r"(b[0]), "r"(b[1]));
}

__device__ __forceinline__ void cp16(uint32_t dst, const void* src) {
    asm volatile("cp.async.cg.shared.global [%0], [%1], 16;" :: "r"(dst), "l"(src));
}
#define CP_COMMIT() asm volatile("cp.async.commit_group;" ::: "memory")
#define CP_WAIT1()  asm volatile("cp.async.wait_group 1;" ::: "memory")
#define CP_WAIT0()  asm volatile("cp.async.wait_group 0;" ::: "memory")

__device__ __forceinline__ float2 bf2f(uint32_t p) {
    float2 r;
    r.x = __uint_as_float(p << 16);
    r.y = __uint_as_float(p & 0xffff0000u);
    return r;
}

__device__ __forceinline__ float dot8(uint4 p, const float* hk) {
    float s = 0.f;
    float2 f;
    f = bf2f(p.x); s = fmaf(f.x, hk[0], s); s = fmaf(f.y, hk[1], s);
    f = bf2f(p.y); s = fmaf(f.x, hk[2], s); s = fmaf(f.y, hk[3], s);
    f = bf2f(p.z); s = fmaf(f.x, hk[4], s); s = fmaf(f.y, hk[5], s);
    f = bf2f(p.w); s = fmaf(f.x, hk[6], s); s = fmaf(f.y, hk[7], s);
    return s;
}

__device__ __forceinline__ uint32_t pack_hl(float v0, float v1, uint32_t& lo) {
    __nv_bfloat16 h0 = __float2bfloat16(v0), h1 = __float2bfloat16(v1);
    float r0 = v0 - __bfloat162float(h0), r1 = v1 - __bfloat162float(h1);
    __nv_bfloat16 l0 = __float2bfloat16(r0), l1 = __float2bfloat16(r1);
    lo = (uint32_t)__bfloat16_as_ushort(l0) | ((uint32_t)__bfloat16_as_ushort(l1) << 16);
    return (uint32_t)__bfloat16_as_ushort(h0) | ((uint32_t)__bfloat16_as_ushort(h1) << 16);
}

__device__ __forceinline__ void cvt4(const float* __restrict__ src,
                                     __nv_bfloat16* __restrict__ hi,
                                     __nv_bfloat16* __restrict__ lo, int i) {
    float4 v = ((const float4*)src)[i];
    float f[4] = {v.x, v.y, v.z, v.w};
    ushort4 H, L;
    unsigned short hs[4], ls[4];
#pragma unroll
    for (int j = 0; j < 4; j++) {
        __nv_bfloat16 h = __float2bfloat16(f[j]);
        float r = f[j] - __bfloat162float(h);
        hs[j] = __bfloat16_as_ushort(h);
        ls[j] = __bfloat16_as_ushort(__float2bfloat16(r));
    }
    H.x = hs[0]; H.y = hs[1]; H.z = hs[2]; H.w = hs[3];
    L.x = ls[0]; L.y = ls[1]; L.z = ls[2]; L.w = ls[3];
    ((ushort4*)hi)[i] = H;
    ((ushort4*)lo)[i] = L;
}

// =====================================================================
// K0: fp32 -> (bf16 hi, bf16 lo) split (large tensors)
// =====================================================================
__global__ void __launch_bounds__(256) k0_cvt(
    const float* __restrict__ src, __nv_bfloat16* __restrict__ hi,
    __nv_bfloat16* __restrict__ lo, int n4)
{
    int i = blockIdx.x * 256 + threadIdx.x;
    if (i >= n4) return;
    cvt4(src, hi, lo, i);
}

// K0w: merged convert for Wd, Wb, C_w (each 64*512 floats = 8192 f4)
__global__ void __launch_bounds__(256) k0w_cvt(
    const float* __restrict__ Wd, const float* __restrict__ Wb,
    const float* __restrict__ Cw)
{
    int i = blockIdx.x * 256 + threadIdx.x;   // 0..24575
    if (i < 8192) {
        cvt4(Wd, g_w2hi, g_w2lo, i);
    } else if (i < 16384) {
        cvt4(Wb, g_w2hi + 64 * DM, g_w2lo + 64 * DM, i - 8192);
    } else {
        cvt4(Cw, g_chi, g_clo, i - 16384);
    }
}

#define K2_STRIDE_B 144

// =====================================================================
// K1t (HMMA): d = sigmoid(u@Wd^T+bd), Bu = u@Wb^T+bb.
// =====================================================================
#define K1_TILE_B   (128 * K2_STRIDE_B)   /* 18432 */
#define K1_STAGE_B  (4 * K1_TILE_B)       /* 73728 */
#define K1_SMEM     (2 * K1_STAGE_B)      /* 147456 */

__global__ void __launch_bounds__(256, 1) k1t_dbu(
    const float* __restrict__ bd, const float* __restrict__ bb)
{
    extern __shared__ char sm[];
    const uint32_t sb = smem_u32(sm);

    const int tid  = threadIdx.x;
    const int warp = tid >> 5;
    const int lane = tid & 31;
    const int wm   = warp >> 2;
    const int wn   = warp & 3;
    const int mb   = blockIdx.x * 128;

    const __nv_bfloat16* srcs[4] = {
        g_uhi + (size_t)mb * DM, g_ulo + (size_t)mb * DM, g_w2hi, g_w2lo };

    float acc[4][4][4];
#pragma unroll
    for (int i = 0; i < 4; i++)
#pragma unroll
        for (int j = 0; j < 4; j++)
#pragma unroll
            for (int q = 0; q < 4; q++) acc[i][j][q] = 0.f;

    const int a_row = (lane & 15);
    const int a_chk = (lane >> 4);
    const int b_row = (lane & 7) + ((lane >> 4) << 3);
    const int b_chk = ((lane >> 3) & 1);

#pragma unroll
    for (int t = 0; t < 4; t++) {
        const __nv_bfloat16* s = srcs[t];
#pragma unroll
        for (int j = 0; j < 4; j++) {
            int f = tid + 256 * j;
            int row = f >> 3, c = f & 7;
            cp16(sb + t * K1_TILE_B + row * K2_STRIDE_B + c * 16,
                 s + (size_t)row * DM + c * 8);
        }
    }
    CP_COMMIT();

    for (int ch = 0; ch < 8; ch++) {
        const uint32_t sbase = sb + (ch & 1) * K1_STAGE_B;
        if (ch < 7) {
            const uint32_t nbase = sb + ((ch + 1) & 1) * K1_STAGE_B;
            const int k0g = (ch + 1) * 64;
#pragma unroll
            for (int t = 0; t < 4; t++) {
                const __nv_bfloat16* s = srcs[t];
#pragma unroll
                for (int j = 0; j < 4; j++) {
                    int f = tid + 256 * j;
                    int row = f >> 3, c = f & 7;
                    cp16(nbase + t * K1_TILE_B + row * K2_STRIDE_B + c * 16,
                         s + (size_t)row * DM + k0g + c * 8);
                }
            }
            CP_COMMIT();
            CP_WAIT1();
        } else {
            CP_WAIT0();
        }
        __syncthreads();

        const uint32_t sAhi = sbase;
        const uint32_t sAlo = sbase + K1_TILE_B;
        const uint32_t sBhi = sbase + 2 * K1_TILE_B;
        const uint32_t sBlo = sbase + 3 * K1_TILE_B;

#pragma unroll
        for (int k16 = 0; k16 < 4; k16++) {
            const int kc = k16 * 2;
            uint32_t bh[4][2], bl[4][2];
#pragma unroll
            for (int g = 0; g < 2; g++) {
                uint32_t r[4];
                ldm_x4(r, sBhi + (wn * 32 + g * 16 + b_row) * K2_STRIDE_B + (kc + b_chk) * 16);
                bh[2 * g][0] = r[0]; bh[2 * g][1] = r[1];
                bh[2 * g + 1][0] = r[2]; bh[2 * g + 1][1] = r[3];
                ldm_x4(r, sBlo + (wn * 32 + g * 16 + b_row) * K2_STRIDE_B + (kc + b_chk) * 16);
                bl[2 * g][0] = r[0]; bl[2 * g][1] = r[1];
                bl[2 * g + 1][0] = r[2]; bl[2 * g + 1][1] = r[3];
            }
#pragma unroll
            for (int mi = 0; mi < 4; mi++) {
                uint32_t ah[4], al[4];
                ldm_x4(ah, sAhi + (wm * 64 + mi * 16 + a_row) * K2_STRIDE_B + (kc + a_chk) * 16);
                ldm_x4(al, sAlo + (wm * 64 + mi * 16 + a_row) * K2_STRIDE_B + (kc + a_chk) * 16);
#pragma unroll
                for (int ni = 0; ni < 4; ni++) {
                    mma_bf16(acc[mi][ni], ah, bh[ni]);
                    mma_bf16(acc[mi][ni], ah, bl[ni]);
                    mma_bf16(acc[mi][ni], al, bh[ni]);
                }
            }
        }
        __syncthreads();
    }

    const int mr = mb + wm * 64 + (lane >> 2);
    const int nc0 = wn * 32 + (lane & 3) * 2;
#pragma unroll
    for (int mi = 0; mi < 4; mi++) {
#pragma unroll
        for (int ni = 0; ni < 4; ni++) {
            int n = nc0 + ni * 8;
#pragma unroll
            for (int half = 0; half < 2; half++) {
                int m = mr + mi * 16 + half * 8;
                float v0 = acc[mi][ni][2 * half];
                float v1 = acc[mi][ni][2 * half + 1];
                if (n < 64) {
                    v0 = 1.f / (1.f + expf(-(v0 + __ldg(bd + n))));
                    v1 = 1.f / (1.f + expf(-(v1 + __ldg(bd + n + 1))));
                    *(float2*)(g_d + (size_t)m * NS + n) = make_float2(v0, v1);
                } else {
                    v0 += __ldg(bb + n - 64);
                    v1 += __ldg(bb + n - 63);
                    *(float2*)(g_Bu + (size_t)m * NS + (n - 64)) = make_float2(v0, v1);
                }
            }
        }
    }
}

// =====================================================================
// K2 (HMMA, cp.async 2-stage, 128x128 tile): A = tanh(u@W_A^T + b)/8,
// diag<-d, output bf16 hi/lo. Single launch, grid (32, 128).
// =====================================================================
#define K2_TILE_B   (128 * K2_STRIDE_B)   /* 18432 */
#define K2_STAGE_B  (4 * K2_TILE_B)       /* 73728 */
#define K2_SMEM     (2 * K2_STAGE_B)      /* 147456 */

__global__ void __launch_bounds__(256, 1) k2h_A(const float* __restrict__ ba)
{
    extern __shared__ char sm[];
    const uint32_t sb = smem_u32(sm);

    const int tid  = threadIdx.x;
    const int warp = tid >> 5;
    const int lane = tid & 31;
    const int wm   = warp >> 2;
    const int wn   = warp & 3;
    const int nb   = blockIdx.x * 128;
    const int mb   = blockIdx.y * 128;

    const __nv_bfloat16* srcs[4] = {
        g_uhi + (size_t)mb * DM, g_ulo + (size_t)mb * DM,
        g_whi + (size_t)nb * DM, g_wlo + (size_t)nb * DM };

    float acc[4][4][4];
#pragma unroll
    for (int i = 0; i < 4; i++)
#pragma unroll
        for (int j = 0; j < 4; j++)
#pragma unroll
            for (int q = 0; q < 4; q++) acc[i][j][q] = 0.f;

    const int a_row = (lane & 15);
    const int a_chk = (lane >> 4);
    const int b_row = (lane & 7) + ((lane >> 4) << 3);
    const int b_chk = ((lane >> 3) & 1);

#pragma unroll
    for (int t = 0; t < 4; t++) {
        const __nv_bfloat16* s = srcs[t];
#pragma unroll
        for (int j = 0; j < 4; j++) {
            int f = tid + 256 * j;
            int row = f >> 3, c = f & 7;
            cp16(sb + t * K2_TILE_B + row * K2_STRIDE_B + c * 16,
                 s + (size_t)row * DM + c * 8);
        }
    }
    CP_COMMIT();

    for (int ch = 0; ch < 8; ch++) {
        const uint32_t sbase = sb + (ch & 1) * K2_STAGE_B;
        if (ch < 7) {
            const uint32_t nbase = sb + ((ch + 1) & 1) * K2_STAGE_B;
            const int k0g = (ch + 1) * 64;
#pragma unroll
            for (int t = 0; t < 4; t++) {
                const __nv_bfloat16* s = srcs[t];
#pragma unroll
                for (int j = 0; j < 4; j++) {
                    int f = tid + 256 * j;
                    int row = f >> 3, c = f & 7;
                    cp16(nbase + t * K2_TILE_B + row * K2_STRIDE_B + c * 16,
                         s + (size_t)row * DM + k0g + c * 8);
                }
            }
            CP_COMMIT();
            CP_WAIT1();
        } else {
            CP_WAIT0();
        }
        __syncthreads();

        const uint32_t sAhi = sbase;
        const uint32_t sAlo = sbase + K2_TILE_B;
        const uint32_t sBhi = sbase + 2 * K2_TILE_B;
        const uint32_t sBlo = sbase + 3 * K2_TILE_B;

#pragma unroll
        for (int k16 = 0; k16 < 4; k16++) {
            const int kc = k16 * 2;
            uint32_t bh[4][2], bl[4][2];
#pragma unroll
            for (int g = 0; g < 2; g++) {
                uint32_t r[4];
                ldm_x4(r, sBhi + (wn * 32 + g * 16 + b_row) * K2_STRIDE_B + (kc + b_chk) * 16);
                bh[2 * g][0] = r[0]; bh[2 * g][1] = r[1];
                bh[2 * g + 1][0] = r[2]; bh[2 * g + 1][1] = r[3];
                ldm_x4(r, sBlo + (wn * 32 + g * 16 + b_row) * K2_STRIDE_B + (kc + b_chk) * 16);
                bl[2 * g][0] = r[0]; bl[2 * g][1] = r[1];
                bl[2 * g + 1][0] = r[2]; bl[2 * g + 1][1] = r[3];
            }
#pragma unroll
            for (int mi = 0; mi < 4; mi++) {
                uint32_t ah[4], al[4];
                ldm_x4(ah, sAhi + (wm * 64 + mi * 16 + a_row) * K2_STRIDE_B + (kc + a_chk) * 16);
                ldm_x4(al, sAlo + (wm * 64 + mi * 16 + a_row) * K2_STRIDE_B + (kc + a_chk) * 16);
#pragma unroll
                for (int ni = 0; ni < 4; ni++) {
                    mma_bf16(acc[mi][ni], ah, bh[ni]);
                    mma_bf16(acc[mi][ni], ah, bl[ni]);
                    mma_bf16(acc[mi][ni], al, bh[ni]);
                }
            }
        }
        __syncthreads();
    }

    // epilogue: bias + tanh*0.125, diag <- d, write bf16 hi/lo pairs
    const int mr = mb + wm * 64 + (lane >> 2);
    const int nc0 = nb + wn * 32 + (lane & 3) * 2;
#pragma unroll
    for (int mi = 0; mi < 4; mi++) {
#pragma unroll
        for (int ni = 0; ni < 4; ni++) {
            int n = nc0 + ni * 8;
            float bias0 = __ldg(ba + n), bias1 = __ldg(ba + n + 1);
            int i0 = n / 64, j0 = n % 64;
            int i1 = (n + 1) / 64, j1 = (n + 1) % 64;
#pragma unroll
            for (int half = 0; half < 2; half++) {
                int m = mr + mi * 16 + half * 8;
                float v0 = tanhf(acc[mi][ni][2 * half] + bias0) * 0.125f;
                float v1 = tanhf(acc[mi][ni][2 * half + 1] + bias1) * 0.125f;
                if (i0 == j0) v0 = g_d[(size_t)m * NS + i0];
                if (i1 == j1) v1 = g_d[(size_t)m * NS + i1];
                uint32_t lo, hi = pack_hl(v0, v1, lo);
                *(uint32_t*)(g_Ahi + (size_t)m * NN + n) = hi;
                *(uint32_t*)(g_Alo + (size_t)m * NN + n) = lo;
            }
        }
    }
}

// =====================================================================
// K3a (pass 1): per-chunk propagator M_c (tensor, bf16 3-prod) + v_c.
// =====================================================================
#define P1_SA(s)   ((s) * 18432)
#define P1_SALO(s) ((s) * 18432 + 9216)
#define P1_MTH     36864
#define P1_MTL     46080
#define P1_SV      55296
#define P1_SBU     55808
#define P1_SMEM    56320

__global__ void __launch_bounds__(256) k3a_prop()
{
    extern __shared__ char sm[];
    const uint32_t sb = smem_u32(sm);
    const int tid = threadIdx.x, warp = tid >> 5, lane = tid & 31;
    const int wm = warp >> 1, wn = warp & 1;
    const int chunk = blockIdx.x, b = blockIdx.y;
    const int cid = b * CHC + chunk;
    const size_t tbase = (size_t)b * TT + (size_t)chunk * CHL;
    const __nv_bfloat16* Ahi = g_Ahi + tbase * NN;
    const __nv_bfloat16* Alo = g_Alo + tbase * NN;
    const float* Bu = g_Bu + tbase * NS;

    for (int f = tid; f < 4096; f += 256) {
        int j = f >> 6, ii = f & 63;
        *(unsigned short*)(sm + P1_MTH + j * 144 + ii * 2) =
            (j == ii) ? (unsigned short)0x3F80 : (unsigned short)0;
        *(unsigned short*)(sm + P1_MTL + j * 144 + ii * 2) = 0;
    }
    if (tid < 64) ((float*)(sm + P1_SV))[tid] = 0.f;

#pragma unroll
    for (int j = 0; j < 2; j++) {
        int f = tid + 256 * j;
        int r2 = f >> 3, c2 = f & 7;
        cp16(sb + P1_SA(0) + r2 * 144 + c2 * 16, Ahi + (size_t)r2 * 64 + c2 * 8);
        cp16(sb + P1_SALO(0) + r2 * 144 + c2 * 16, Alo + (size_t)r2 * 64 + c2 * 8);
    }
    if (tid < 16) cp16(sb + P1_SBU + tid * 16, Bu + tid * 4);
    CP_COMMIT();
    __syncthreads();

    const int a_row = lane & 15, a_chk = lane >> 4;
    const int b_row = (lane & 7) + ((lane >> 4) << 3);
    const int b_chk = (lane >> 3) & 1;
    const int vi = tid >> 2, vq = tid & 3;

    float acc[4][4];

    for (int t = 0; t < CHL; t++) {
        const int s = t & 1;
        if (t < CHL - 1) {
            const int s1 = s ^ 1;
#pragma unroll
            for (int j = 0; j < 2; j++) {
                int f = tid + 256 * j;
                int r2 = f >> 3, c2 = f & 7;
                cp16(sb + P1_SA(s1) + r2 * 144 + c2 * 16,
                     Ahi + (size_t)(t + 1) * NN + r2 * 64 + c2 * 8);
                cp16(sb + P1_SALO(s1) + r2 * 144 + c2 * 16,
                     Alo + (size_t)(t + 1) * NN + r2 * 64 + c2 * 8);
            }
            if (tid < 16) cp16(sb + P1_SBU + s1 * 256 + tid * 16,
                               Bu + (size_t)(t + 1) * NS + tid * 4);
            CP_COMMIT();
            CP_WAIT1();
        } else {
            CP_WAIT0();
        }
        __syncthreads();

#pragma unroll
        for (int ni = 0; ni < 4; ni++)
#pragma unroll
            for (int q = 0; q < 4; q++) acc[ni][q] = 0.f;

        const uint32_t sAh = sb + P1_SA(s), sAl = sb + P1_SALO(s);
#pragma unroll
        for (int k16 = 0; k16 < 4; k16++) {
            const int kc = k16 * 2;
            uint32_t bh[4][2], bl[4][2];
#pragma unroll
            for (int g = 0; g < 2; g++) {
                uint32_t r[4];
                ldm_x4(r, sb + P1_MTH + (wn * 32 + g * 16 + b_row) * 144 + (kc + b_chk) * 16);
                bh[2 * g][0] = r[0]; bh[2 * g][1] = r[1];
                bh[2 * g + 1][0] = r[2]; bh[2 * g + 1][1] = r[3];
                ldm_x4(r, sb + P1_MTL + (wn * 32 + g * 16 + b_row) * 144 + (kc + b_chk) * 16);
                bl[2 * g][0] = r[0]; bl[2 * g][1] = r[1];
                bl[2 * g + 1][0] = r[2]; bl[2 * g + 1][1] = r[3];
            }
            uint32_t ah[4], al[4];
            ldm_x4(ah, sAh + (wm * 16 + a_row) * 144 + (kc + a_chk) * 16);
            ldm_x4(al, sAl + (wm * 16 + a_row) * 144 + (kc + a_chk) * 16);
#pragma unroll
            for (int ni = 0; ni < 4; ni++) mma_bf16(acc[ni], ah, bh[ni]);
#pragma unroll
            for (int ni = 0; ni < 4; ni++) mma_bf16(acc[ni], ah, bl[ni]);
#pragma unroll
            for (int ni = 0; ni < 4; ni++) mma_bf16(acc[ni], al, bh[ni]);
        }

        const char* pA = sm + P1_SA(s) + vi * 144 + vq * 32;
        uint4 vh0 = ((const uint4*)pA)[0], vh1 = ((const uint4*)pA)[1];
        const char* pL = sm + P1_SALO(s) + vi * 144 + vq * 32;
        uint4 vl0 = ((const uint4*)pL)[0], vl1 = ((const uint4*)pL)[1];
        const float* svp = (const float*)(sm + P1_SV) + s * 64 + vq * 16;
        float hk[16];
#pragma unroll
        for (int j = 0; j < 4; j++) {
            float4 hv = ((const float4*)svp)[j];
            hk[4 * j] = hv.x; hk[4 * j + 1] = hv.y; hk[4 * j + 2] = hv.z; hk[4 * j + 3] = hv.w;
        }
        float part = dot8(vh0, hk) + dot8(vh1, hk + 8) + dot8(vl0, hk) + dot8(vl1, hk + 8);
        part += __shfl_xor_sync(0xffffffffu, part, 1);
        part += __shfl_xor_sync(0xffffffffu, part, 2);
        float bu = 0.f;
        if (vq == 0) bu = ((const float*)(sm + P1_SBU))[s * 64 + vi];
        __syncthreads();

#pragma unroll
        for (int ni = 0; ni < 4; ni++) {
            int j0 = wn * 32 + ni * 8 + (lane & 3) * 2;
            int i0 = wm * 16 + (lane >> 2);
#pragma unroll
            for (int e = 0; e < 4; e++) {
                int jj = j0 + (e & 1);
                int ii = i0 + (e >> 1) * 8;
                float v = acc[ni][e];
                __nv_bfloat16 hbf = __float2bfloat16(v);
                float r = v - __bfloat162float(hbf);
                *(unsigned short*)(sm + P1_MTH + jj * 144 + ii * 2) = __bfloat16_as_ushort(hbf);
                *(unsigned short*)(sm + P1_MTL + jj * 144 + ii * 2) =
                    __bfloat16_as_ushort(__float2bfloat16(r));
            }
        }
        if (vq == 0) ((float*)(sm + P1_SV))[(s ^ 1) * 64 + vi] = part + bu;
        __syncthreads();
    }

#pragma unroll
    for (int ni = 0; ni < 4; ni++) {
        int j0 = wn * 32 + ni * 8 + (lane & 3) * 2;
        int i0 = wm * 16 + (lane >> 2);
        *(float2*)(g_M + (size_t)cid * NN + (size_t)i0 * 64 + j0) = make_float2(acc[ni][0], acc[ni][1]);
        *(float2*)(g_M + (size_t)cid * NN + (size_t)(i0 + 8) * 64 + j0) = make_float2(acc[ni][2], acc[ni][3]);
    }
    if (tid < 64) g_v[(size_t)cid * NS + tid] = ((const float*)(sm + P1_SV))[tid];
}

// =====================================================================
// K3b (pass 2): serial combine across chunks per batch.
// =====================================================================
__global__ void __launch_bounds__(256) k3b_comb()
{
    const int b = blockIdx.x, tid = threadIdx.x;
    const int i = tid >> 2, q = tid & 3;
    __shared__ float H[64];
    if (tid < 64) H[tid] = 0.f;
    __syncthreads();

    const float* Mb = g_M + (size_t)b * CHC * NN + (size_t)i * 64 + q * 16;
    const float* vb = g_v + (size_t)b * CHC * NS + i;

    float4 c0, c1, c2, c3, d0, d1, d2, d3;
    float4 e0 = make_float4(0, 0, 0, 0), e1 = e0, e2 = e0, e3 = e0;
    float vc = 0.f, vn = 0.f, ve = 0.f;

    {
        const float4* p = (const float4*)Mb;
        c0 = p[0]; c1 = p[1]; c2 = p[2]; c3 = p[3];
        p = (const float4*)(Mb + NN);
        d0 = p[0]; d1 = p[1]; d2 = p[2]; d3 = p[3];
        if (q == 0) { vc = vb[0]; vn = vb[NS]; }
    }

    for (int c = 0; c < CHC; c++) {
        if (c + 2 < CHC) {
            const float4* p = (const float4*)(Mb + (size_t)(c + 2) * NN);
            e0 = p[0]; e1 = p[1]; e2 = p[2]; e3 = p[3];
            if (q == 0) ve = vb[(size_t)(c + 2) * NS];
        }
        float hst = 0.f;
        if (tid < 64) hst = H[tid];
        const float* hv = H + q * 16;
        float4 h0 = *(const float4*)(hv);
        float4 h1 = *(const float4*)(hv + 4);
        float4 h2 = *(const float4*)(hv + 8);
        float4 h3 = *(const float4*)(hv + 12);

        float p4 = c0.x * h0.x + c0.y * h0.y + c0.z * h0.z + c0.w * h0.w;
        p4 += c1.x * h1.x + c1.y * h1.y + c1.z * h1.z + c1.w * h1.w;
        p4 += c2.x * h2.x + c2.y * h2.y + c2.z * h2.z + c2.w * h2.w;
        p4 += c3.x * h3.x + c3.y * h3.y + c3.z * h3.z + c3.w * h3.w;
        p4 += __shfl_xor_sync(0xffffffffu, p4, 1);
        p4 += __shfl_xor_sync(0xffffffffu, p4, 2);
        __syncthreads();

        if (tid < 64) g_Hs[(size_t)(b * CHC + c) * NS + tid] = hst;
        if (q == 0) H[i] = p4 + vc;
        __syncthreads();

        c0 = d0; c1 = d1; c2 = d2; c3 = d3;
        d0 = e0; d1 = e1; d2 = e2; d3 = e3;
        vc = vn; vn = ve;
    }
}

// =====================================================================
// K3c (pass 3): local scans from true start states; emit hs hi/lo.
// =====================================================================
__global__ void __launch_bounds__(256) k3c_scan()
{
    const int chunk = blockIdx.x, b = blockIdx.y, tid = threadIdx.x;
    const int i = tid >> 2, q = tid & 3;
    const int cid = b * CHC + chunk;
    const size_t tbase = (size_t)b * TT + (size_t)chunk * CHL;

    __shared__ float h[2][64];
    if (tid < 64) h[0][tid] = g_Hs[(size_t)cid * NS + tid];
    __syncthreads();

    const __nv_bfloat16* Ah = g_Ahi + tbase * NN + (size_t)i * 64 + q * 16;
    const __nv_bfloat16* Al = g_Alo + tbase * NN + (size_t)i * 64 + q * 16;
    const float* BuB = g_Bu + tbase * NS + i;
    __nv_bfloat16* hsHi = g_hshi + tbase * NS + i;
    __nv_bfloat16* hsLo = g_hslo + tbase * NS + i;

    uint4 ch0, ch1, cl0, cl1, nh0, nh1, nl0, nl1;
    uint4 eh0 = make_uint4(0, 0, 0, 0), eh1 = eh0, el0 = eh0, el1 = eh0;
    float buc = 0.f, bun = 0.f, bue = 0.f;

    {
        ch0 = ((const uint4*)Ah)[0]; ch1 = ((const uint4*)Ah)[1];
        cl0 = ((const uint4*)Al)[0]; cl1 = ((const uint4*)Al)[1];
        nh0 = ((const uint4*)(Ah + NN))[0]; nh1 = ((const uint4*)(Ah + NN))[1];
        nl0 = ((const uint4*)(Al + NN))[0]; nl1 = ((const uint4*)(Al + NN))[1];
        if (q == 0) { buc = BuB[0]; bun = BuB[NS]; }
    }

    for (int t = 0; t < CHL; t++) {
        if (t + 2 < CHL) {
            eh0 = ((const uint4*)(Ah + (size_t)(t + 2) * NN))[0];
            eh1 = ((const uint4*)(Ah + (size_t)(t + 2) * NN))[1];
            el0 = ((const uint4*)(Al + (size_t)(t + 2) * NN))[0];
            el1 = ((const uint4*)(Al + (size_t)(t + 2) * NN))[1];
            if (q == 0) bue = BuB[(size_t)(t + 2) * NS];
        }
        const float* hv = h[t & 1] + q * 16;
        float hk[16];
#pragma unroll
        for (int j = 0; j < 4; j++) {
            float4 x = ((const float4*)hv)[j];
            hk[4 * j] = x.x; hk[4 * j + 1] = x.y; hk[4 * j + 2] = x.z; hk[4 * j + 3] = x.w;
        }
        float p4 = dot8(ch0, hk) + dot8(ch1, hk + 8) + dot8(cl0, hk) + dot8(cl1, hk + 8);
        p4 += __shfl_xor_sync(0xffffffffu, p4, 1);
        p4 += __shfl_xor_sync(0xffffffffu, p4, 2);

        if (q == 0) {
            float nh = p4 + buc;
            h[(t & 1) ^ 1][i] = nh;
            __nv_bfloat16 hb = __float2bfloat16(nh);
            hsHi[(size_t)t * NS] = hb;
            hsLo[(size_t)t * NS] = __float2bfloat16(nh - __bfloat162float(hb));
        }
        __syncthreads();

        ch0 = nh0; ch1 = nh1; cl0 = nl0; cl1 = nl1;
        nh0 = eh0; nh1 = eh1; nl0 = el0; nl1 = el1;
        buc = bun; bun = bue;
    }
}

// =====================================================================
// K4t (HMMA): out = hs @ C^T + D * u.
// =====================================================================
#define K4_TILE_B  (128 * K2_STRIDE_B)    /* 18432 */
#define K4_SMEM    (4 * K4_TILE_B)        /* 73728 */

__global__ void __launch_bounds__(256, 1) k4t_out(
    const float* __restrict__ Dv, const float* __restrict__ u,
    float* __restrict__ out)
{
    extern __shared__ char sm[];
    const uint32_t sb = smem_u32(sm);

    const int tid  = threadIdx.x;
    const int warp = tid >> 5;
    const int lane = tid & 31;
    const int wm   = warp >> 2;
    const int wn   = warp & 3;
    const int nb   = blockIdx.x * 128;
    const int mb   = blockIdx.y * 128;

    const __nv_bfloat16* srcs[4] = {
        g_hshi + (size_t)mb * NS, g_hslo + (size_t)mb * NS,
        g_chi + (size_t)nb * NS, g_clo + (size_t)nb * NS };

#pragma unroll
    for (int t = 0; t < 4; t++) {
        const __nv_bfloat16* s = srcs[t];
#pragma unroll
        for (int j = 0; j < 4; j++) {
            int f = tid + 256 * j;
            int row = f >> 3, c = f & 7;
            cp16(sb + t * K4_TILE_B + row * K2_STRIDE_B + c * 16,
                 s + (size_t)row * NS + c * 8);
        }
    }
    CP_COMMIT();
    CP_WAIT0();
    __syncthreads();

    float acc[4][4][4];
#pragma unroll
    for (int i = 0; i < 4; i++)
#pragma unroll
        for (int j = 0; j < 4; j++)
#pragma unroll
            for (int q = 0; q < 4; q++) acc[i][j][q] = 0.f;

    const int a_row = (lane & 15);
    const int a_chk = (lane >> 4);
    const int b_row = (lane & 7) + ((lane >> 4) << 3);
    const int b_chk = ((lane >> 3) & 1);

    const uint32_t sAhi = sb;
    const uint32_t sAlo = sb + K4_TILE_B;
    const uint32_t sBhi = sb + 2 * K4_TILE_B;
    const uint32_t sBlo = sb + 3 * K4_TILE_B;

#pragma unroll
    for (int k16 = 0; k16 < 4; k16++) {
        const int kc = k16 * 2;
        uint32_t bh[4][2], bl[4][2];
#pragma unroll
        for (int g = 0; g < 2; g++) {
            uint32_t r[4];
            ldm_x4(r, sBhi + (wn * 32 + g * 16 + b_row) * K2_STRIDE_B + (kc + b_chk) * 16);
            bh[2 * g][0] = r[0]; bh[2 * g][1] = r[1];
            bh[2 * g + 1][0] = r[2]; bh[2 * g + 1][1] = r[3];
            ldm_x4(r, sBlo + (wn * 32 + g * 16 + b_row) * K2_STRIDE_B + (kc + b_chk) * 16);
            bl[2 * g][0] = r[0]; bl[2 * g][1] = r[1];
            bl[2 * g + 1][0] = r[2]; bl[2 * g + 1][1] = r[3];
        }
#pragma unroll
        for (int mi = 0; mi < 4; mi++) {
            uint32_t ah[4], al[4];
            ldm_x4(ah, sAhi + (wm * 64 + mi * 16 + a_row) * K2_STRIDE_B + (kc + a_chk) * 16);
            ldm_x4(al, sAlo + (wm * 64 + mi * 16 + a_row) * K2_STRIDE_B + (kc + a_chk) * 16);
#pragma unroll
            for (int ni = 0; ni < 4; ni++) {
                mma_bf16(acc[mi][ni], ah, bh[ni]);
                mma_bf16(acc[mi][ni], ah, bl[ni]);
                mma_bf16(acc[mi][ni], al, bh[ni]);
            }
        }
    }

    const int mr = mb + wm * 64 + (lane >> 2);
    const int nc0 = nb + wn * 32 + (lane & 3) * 2;
#pragma unroll
    for (int mi = 0; mi < 4; mi++) {
#pragma unroll
        for (int ni = 0; ni < 4; ni++) {
            int n = nc0 + ni * 8;
            float d0 = __ldg(Dv + n), d1 = __ldg(Dv + n + 1);
#pragma unroll
            for (int half = 0; half < 2; half++) {
                int m = mr + mi * 16 + half * 8;
                float2 uu = *(const float2*)(u + (size_t)m * DM + n);
                float v0 = acc[mi][ni][2 * half] + d0 * uu.x;
                float v1 = acc[mi][ni][2 * half + 1] + d1 * uu.y;
                *(float2*)(out + (size_t)m * DM + n) = make_float2(v0, v1);
            }
        }
    }
}

// =====================================================================
extern "C" void kernel_launch(void* const* d_in, const int* in_sizes, int n_in,
                              void* d_out, int out_size)
{
    const float* u    = (const float*)d_in[0];
    const float* Wd_w = (const float*)d_in[1];
    const float* Wd_b = (const float*)d_in[2];
    const float* WA_w = (const float*)d_in[3];
    const float* WA_b = (const float*)d_in[4];
    const float* WB_w = (const float*)d_in[5];
    const float* WB_b = (const float*)d_in[6];
    const float* C_w  = (const float*)d_in[7];
    const float* Dv   = (const float*)d_in[8];
    float* out = (float*)d_out;

    static int init_done = 0;
    if (!init_done) {
        cudaFuncSetAttribute(k2h_A, cudaFuncAttributeMaxDynamicSharedMemorySize, K2_SMEM);
        cudaFuncSetAttribute(k1t_dbu, cudaFuncAttributeMaxDynamicSharedMemorySize, K1_SMEM);
        cudaFuncSetAttribute(k4t_out, cudaFuncAttributeMaxDynamicSharedMemorySize, K4_SMEM);
        cudaFuncSetAttribute(k3a_prop, cudaFuncAttributeMaxDynamicSharedMemorySize, P1_SMEM);
        init_done = 1;
    }

    __nv_bfloat16 *uhi, *ulo, *whi, *wlo;
    cudaGetSymbolAddress((void**)&uhi, g_uhi);
    cudaGetSymbolAddress((void**)&ulo, g_ulo);
    cudaGetSymbolAddress((void**)&whi, g_whi);
    cudaGetSymbolAddress((void**)&wlo, g_wlo);

    int n4u = (BT * DM) / 4;
    int n4w = (NN * DM) / 4;
    k0_cvt<<<(n4u + 255) / 256, 256>>>(u, uhi, ulo, n4u);
    k0_cvt<<<(n4w + 255) / 256, 256>>>(WA_w, whi, wlo, n4w);
    k0w_cvt<<<96, 256>>>(Wd_w, WB_w, C_w);
    k1t_dbu<<<BT / 128, 256, K1_SMEM>>>(Wd_b, WB_b);
    k2h_A<<<dim3(NN / 128, BT / 128), 256, K2_SMEM>>>(WA_b);
    k3a_prop<<<dim3(CHC, BATCH), 256, P1_SMEM>>>();
    k3b_comb<<<BATCH, 256>>>();
    k3c_scan<<<dim3(CHC, BATCH), 256>>>();
    k4t_out<<<dim3(DM / 128, BT / 128), 256, K4_SMEM>>>(Dv, u, out);
}